// round 2
// baseline (speedup 1.0000x reference)
#include <cuda_runtime.h>
#include <cuda_bf16.h>
#include <math.h>

// ---------------------------------------------------------------------------
// Problem constants
// ---------------------------------------------------------------------------
#define BB   2
#define NN_  4096
#define DD   640
#define HH   8
#define DH   80
#define CN_  77
#define CDIM 768
#define FF_  2560
#define EPS_ 1e-5f
#define SCALE_ATTN 0.11180339887498948f   // 80^-0.5

// ---------------------------------------------------------------------------
// Device scratch (static allocation — no cudaMalloc allowed). ~370 MB total.
// ---------------------------------------------------------------------------
__device__ float g_x   [(size_t)BB * NN_ * DD];           // running residual
__device__ float g_h   [(size_t)BB * NN_ * DD];           // LN output
__device__ float g_q   [(size_t)BB * NN_ * DD];
__device__ float g_k   [(size_t)BB * NN_ * DD];
__device__ float g_v   [(size_t)BB * NN_ * DD];
__device__ float g_attn[(size_t)BB * NN_ * DD];
__device__ float g_proj[(size_t)BB * NN_ * 2 * FF_];      // GEGLU projection
__device__ float g_ffh [(size_t)BB * NN_ * FF_];          // a * gelu(g)

// ---------------------------------------------------------------------------
// Generic tiled fp32 GEMM.  C = alpha*A@B (+bias) (+resid)
//   A: row-major [M,K] lda;  B: [K,N] ldb row-major
// ---------------------------------------------------------------------------
template<int BM, int BN, int BK, int TM, int TN>
__global__ __launch_bounds__(256, 2)
void gemm_k(const float* __restrict__ A, const float* __restrict__ B,
            float* __restrict__ C,
            int M, int N, int K, int lda, int ldb, int ldc,
            const float* __restrict__ bias,
            const float* __restrict__ resid,
            float alpha)
{
    constexpr int TX = BN / TN;                 // threads along N
    __shared__ float As[BK][BM];
    __shared__ float Bs[BK][BN];

    const int tid = threadIdx.x;
    const int tx  = tid % TX;
    const int ty  = tid / TX;
    const int m0  = blockIdx.y * BM;
    const int n0  = blockIdx.x * BN;

    float acc[TM][TN];
    #pragma unroll
    for (int i = 0; i < TM; i++)
        #pragma unroll
        for (int j = 0; j < TN; j++) acc[i][j] = 0.f;

    float ar[TM], br[TN];

    for (int k0 = 0; k0 < K; k0 += BK) {
        #pragma unroll 4
        for (int idx = tid; idx < BM * BK; idx += 256) {
            int m = idx / BK, kk = idx % BK;
            float v = 0.f;
            if (m0 + m < M && k0 + kk < K)
                v = A[(long)(m0 + m) * lda + (k0 + kk)];
            As[kk][m] = v;
        }
        #pragma unroll 4
        for (int idx = tid; idx < BK * BN; idx += 256) {
            int kk = idx / BN, n = idx % BN;
            float v = 0.f;
            if (k0 + kk < K && n0 + n < N)
                v = B[(long)(k0 + kk) * ldb + (n0 + n)];
            Bs[kk][n] = v;
        }
        __syncthreads();

        #pragma unroll
        for (int kk = 0; kk < BK; kk++) {
            #pragma unroll
            for (int i = 0; i < TM; i++) ar[i] = As[kk][ty * TM + i];
            #pragma unroll
            for (int j = 0; j < TN; j++) br[j] = Bs[kk][tx * TN + j];
            #pragma unroll
            for (int i = 0; i < TM; i++)
                #pragma unroll
                for (int j = 0; j < TN; j++)
                    acc[i][j] += ar[i] * br[j];
        }
        __syncthreads();
    }

    #pragma unroll
    for (int i = 0; i < TM; i++) {
        int m = m0 + ty * TM + i;
        if (m >= M) continue;
        #pragma unroll
        for (int j = 0; j < TN; j++) {
            int n = n0 + tx * TN + j;
            if (n >= N) continue;
            float v = acc[i][j] * alpha;
            if (bias)  v += bias[n];
            if (resid) v += resid[(long)m * ldc + n];
            C[(long)m * ldc + n] = v;
        }
    }
}

// ---------------------------------------------------------------------------
// Fused flash self-attention (fp32, online softmax).
//   Per block: 64 query rows of one (b,h); loops over keys in tiles of 32.
//   Q,K,V,O: [B*N, D] row-major, head slice at column h*DH.
//   Static smem: Qs 20.2KB + KVs 10.1KB + Ps 8.25KB = 38.6KB (< 48KB)
// ---------------------------------------------------------------------------
#define FBM 64
#define FBN 32

__global__ __launch_bounds__(256)
void flash_k(const float* __restrict__ Q, const float* __restrict__ K,
             const float* __restrict__ V, float* __restrict__ O)
{
    __shared__ float Qs [FBM][DH + 1];   // [64][81]
    __shared__ float KVs[FBN][DH + 1];   // [32][81]  (K tile, then reused for V)
    __shared__ float Ps [FBM][FBN + 1];  // [64][33]

    const int tid = threadIdx.x;
    const int tx  = tid % 16;            // 16 groups along keys / out-cols
    const int ty  = tid / 16;            // 16 groups along query rows
    const int bh  = blockIdx.y;
    const int b   = bh / HH, h = bh % HH;
    const int row0 = blockIdx.x * FBM;

    const float* Qp = Q + (long)b * NN_ * DD + h * DH;
    const float* Kp = K + (long)b * NN_ * DD + h * DH;
    const float* Vp = V + (long)b * NN_ * DD + h * DH;
    float*       Op = O + (long)b * NN_ * DD + h * DH;

    // ---- load Q tile (64 x 80) via float4 ----
    for (int idx = tid; idx < FBM * (DH / 4); idx += 256) {
        int r = idx / (DH / 4), c = idx % (DH / 4);
        float4 v = *(const float4*)(Qp + (long)(row0 + r) * DD + c * 4);
        Qs[r][c * 4 + 0] = v.x; Qs[r][c * 4 + 1] = v.y;
        Qs[r][c * 4 + 2] = v.z; Qs[r][c * 4 + 3] = v.w;
    }

    float m[4], l[4], acc[4][5];
    #pragma unroll
    for (int i = 0; i < 4; i++) {
        m[i] = -1e30f; l[i] = 0.f;
        #pragma unroll
        for (int j = 0; j < 5; j++) acc[i][j] = 0.f;
    }

    for (int kt = 0; kt < NN_ / FBN; kt++) {
        __syncthreads();   // previous PV phase done with KVs
        // ---- load K tile (32 x 80) ----
        for (int idx = tid; idx < FBN * (DH / 4); idx += 256) {
            int r = idx / (DH / 4), c = idx % (DH / 4);
            float4 v = *(const float4*)(Kp + (long)(kt * FBN + r) * DD + c * 4);
            KVs[r][c * 4 + 0] = v.x; KVs[r][c * 4 + 1] = v.y;
            KVs[r][c * 4 + 2] = v.z; KVs[r][c * 4 + 3] = v.w;
        }
        __syncthreads();

        // ---- S = scale * Q @ K^T   (each thread: 4 rows x 2 cols) ----
        float s[4][2];
        #pragma unroll
        for (int i = 0; i < 4; i++) { s[i][0] = 0.f; s[i][1] = 0.f; }
        #pragma unroll 4
        for (int d = 0; d < DH; d++) {
            float a0 = Qs[ty * 4 + 0][d];
            float a1 = Qs[ty * 4 + 1][d];
            float a2 = Qs[ty * 4 + 2][d];
            float a3 = Qs[ty * 4 + 3][d];
            float b0 = KVs[tx * 2 + 0][d];
            float b1 = KVs[tx * 2 + 1][d];
            s[0][0] += a0 * b0; s[0][1] += a0 * b1;
            s[1][0] += a1 * b0; s[1][1] += a1 * b1;
            s[2][0] += a2 * b0; s[2][1] += a2 * b1;
            s[3][0] += a3 * b0; s[3][1] += a3 * b1;
        }

        // ---- online softmax update ----
        #pragma unroll
        for (int i = 0; i < 4; i++) {
            float rm = fmaxf(s[i][0], s[i][1]) * SCALE_ATTN;
            #pragma unroll
            for (int o = 8; o > 0; o >>= 1)
                rm = fmaxf(rm, __shfl_xor_sync(0xffffffffu, rm, o));
            float mn = fmaxf(m[i], rm);
            float corr = __expf(m[i] - mn);
            float p0 = __expf(s[i][0] * SCALE_ATTN - mn);
            float p1 = __expf(s[i][1] * SCALE_ATTN - mn);
            float rs = p0 + p1;
            #pragma unroll
            for (int o = 8; o > 0; o >>= 1)
                rs += __shfl_xor_sync(0xffffffffu, rs, o);
            l[i] = l[i] * corr + rs;
            m[i] = mn;
            #pragma unroll
            for (int j = 0; j < 5; j++) acc[i][j] *= corr;
            Ps[ty * 4 + i][tx * 2 + 0] = p0;
            Ps[ty * 4 + i][tx * 2 + 1] = p1;
        }
        __syncthreads();   // K reads + Ps writes complete

        // ---- load V tile into same buffer ----
        for (int idx = tid; idx < FBN * (DH / 4); idx += 256) {
            int r = idx / (DH / 4), c = idx % (DH / 4);
            float4 v = *(const float4*)(Vp + (long)(kt * FBN + r) * DD + c * 4);
            KVs[r][c * 4 + 0] = v.x; KVs[r][c * 4 + 1] = v.y;
            KVs[r][c * 4 + 2] = v.z; KVs[r][c * 4 + 3] = v.w;
        }
        __syncthreads();

        // ---- O += P @ V  (each thread: 4 rows x 5 cols) ----
        #pragma unroll 4
        for (int kk = 0; kk < FBN; kk++) {
            float p0 = Ps[ty * 4 + 0][kk];
            float p1 = Ps[ty * 4 + 1][kk];
            float p2 = Ps[ty * 4 + 2][kk];
            float p3 = Ps[ty * 4 + 3][kk];
            #pragma unroll
            for (int j = 0; j < 5; j++) {
                float vv = KVs[kk][tx * 5 + j];
                acc[0][j] += p0 * vv;
                acc[1][j] += p1 * vv;
                acc[2][j] += p2 * vv;
                acc[3][j] += p3 * vv;
            }
        }
    }

    // ---- finalize ----
    #pragma unroll
    for (int i = 0; i < 4; i++) {
        float inv = 1.f / l[i];
        #pragma unroll
        for (int j = 0; j < 5; j++)
            Op[(long)(row0 + ty * 4 + i) * DD + tx * 5 + j] = acc[i][j] * inv;
    }
}

// ---------------------------------------------------------------------------
// LayerNorm: one block per row of length DD=640
// ---------------------------------------------------------------------------
__global__ void ln_k(const float* __restrict__ x, const float* __restrict__ w,
                     const float* __restrict__ b, float* __restrict__ out)
{
    __shared__ float red[256];
    __shared__ float red2[256];
    const long row = blockIdx.x;
    const float* p = x + row * DD;
    float s = 0.f, ss = 0.f;
    float lv[3];
    int cnt = 0;
    for (int idx = threadIdx.x; idx < DD; idx += 256) {
        float v = p[idx];
        lv[cnt++] = v;
        s += v; ss += v * v;
    }
    red[threadIdx.x] = s; red2[threadIdx.x] = ss;
    __syncthreads();
    for (int st = 128; st > 0; st >>= 1) {
        if (threadIdx.x < st) {
            red[threadIdx.x]  += red[threadIdx.x + st];
            red2[threadIdx.x] += red2[threadIdx.x + st];
        }
        __syncthreads();
    }
    const float mean = red[0] * (1.f / DD);
    const float var  = red2[0] * (1.f / DD) - mean * mean;
    const float inv  = rsqrtf(var + EPS_);
    float* o = out + row * DD;
    cnt = 0;
    for (int idx = threadIdx.x; idx < DD; idx += 256) {
        o[idx] = (lv[cnt++] - mean) * inv * w[idx] + b[idx];
    }
}

// ---------------------------------------------------------------------------
// Fused cross-attention: 77 keys, one warp per query row.
// ---------------------------------------------------------------------------
__global__ void xattn_k(const float* __restrict__ Q, const float* __restrict__ K,
                        const float* __restrict__ V, float* __restrict__ O)
{
    __shared__ float qbuf[8][DH];
    __shared__ float sc[8][80];
    const int wid  = threadIdx.x >> 5;
    const int lane = threadIdx.x & 31;
    const long wg  = (long)blockIdx.x * 8 + wid;
    const int q  = (int)(wg % NN_);
    const int bh = (int)(wg / NN_);
    const int h  = bh % HH;
    const int b  = bh / HH;

    const float* qp = Q + ((long)(b * NN_ + q) * DD + h * DH);
    for (int d = lane; d < DH; d += 32) qbuf[wid][d] = qp[d];
    __syncwarp();

    float mx = -1e30f;
    for (int j = lane; j < CN_; j += 32) {
        const float* kp = K + ((long)(b * CN_ + j) * DD + h * DH);
        float s = 0.f;
        #pragma unroll
        for (int d = 0; d < DH; d++) s += qbuf[wid][d] * kp[d];
        s *= SCALE_ATTN;
        sc[wid][j] = s;
        mx = fmaxf(mx, s);
    }
    #pragma unroll
    for (int o = 16; o > 0; o >>= 1) mx = fmaxf(mx, __shfl_xor_sync(0xffffffff, mx, o));

    float sum = 0.f;
    __syncwarp();
    for (int j = lane; j < CN_; j += 32) {
        float e = __expf(sc[wid][j] - mx);
        sc[wid][j] = e;
        sum += e;
    }
    #pragma unroll
    for (int o = 16; o > 0; o >>= 1) sum += __shfl_xor_sync(0xffffffff, sum, o);
    const float inv = 1.f / sum;
    __syncwarp();

    float* op = O + ((long)(b * NN_ + q) * DD + h * DH);
    for (int d = lane; d < DH; d += 32) {
        float acc = 0.f;
        #pragma unroll 7
        for (int j = 0; j < CN_; j++)
            acc += sc[wid][j] * V[(long)(b * CN_ + j) * DD + h * DH + d];
        op[d] = acc * inv;
    }
}

// ---------------------------------------------------------------------------
// GEGLU: out[i,j] = a * gelu_exact(g)
// ---------------------------------------------------------------------------
__global__ void geglu_k(const float* __restrict__ proj, float* __restrict__ out)
{
    const long idx = (long)blockIdx.x * blockDim.x + threadIdx.x;
    const long total = (long)BB * NN_ * FF_;
    if (idx >= total) return;
    const long row = idx / FF_;
    const long col = idx % FF_;
    const float a = proj[row * (2 * FF_) + col];
    const float g = proj[row * (2 * FF_) + FF_ + col];
    const float gelu = 0.5f * g * (1.f + erff(g * 0.70710678118654752f));
    out[row * FF_ + col] = a * gelu;
}

// ---------------------------------------------------------------------------
// Host-side launch helpers
// ---------------------------------------------------------------------------
static inline void gemm_nn(const float* A, const float* B, float* C,
                           int M, int N, int K, int lda, int ldb, int ldc,
                           const float* bias, const float* resid, float alpha = 1.f)
{
    dim3 grid((N + 127) / 128, (M + 127) / 128, 1);
    gemm_k<128,128,16,8,8><<<grid, 256>>>(A, B, C, M, N, K, lda, ldb, ldc,
                                          bias, resid, alpha);
}

extern "C" void kernel_launch(void* const* d_in, const int* in_sizes, int n_in,
                              void* d_out, int out_size)
{
    const float* x      = (const float*)d_in[0];
    const float* ctx    = (const float*)d_in[1];
    const float* ln1w   = (const float*)d_in[2];
    const float* ln1b   = (const float*)d_in[3];
    const float* ln2w   = (const float*)d_in[4];
    const float* ln2b   = (const float*)d_in[5];
    const float* ln3w   = (const float*)d_in[6];
    const float* ln3b   = (const float*)d_in[7];
    const float* wq1    = (const float*)d_in[8];
    const float* wk1    = (const float*)d_in[9];
    const float* wv1    = (const float*)d_in[10];
    const float* wo1    = (const float*)d_in[11];
    const float* bo1    = (const float*)d_in[12];
    const float* wq2    = (const float*)d_in[13];
    const float* wk2    = (const float*)d_in[14];
    const float* wv2    = (const float*)d_in[15];
    const float* wo2    = (const float*)d_in[16];
    const float* bo2    = (const float*)d_in[17];
    const float* wff1   = (const float*)d_in[18];
    const float* bff1   = (const float*)d_in[19];
    const float* wff2   = (const float*)d_in[20];
    const float* bff2   = (const float*)d_in[21];
    float* out = (float*)d_out;

    float *xp, *hp, *qp, *kp, *vp, *ap, *pp, *fp;
    cudaGetSymbolAddress((void**)&xp, g_x);
    cudaGetSymbolAddress((void**)&hp, g_h);
    cudaGetSymbolAddress((void**)&qp, g_q);
    cudaGetSymbolAddress((void**)&kp, g_k);
    cudaGetSymbolAddress((void**)&vp, g_v);
    cudaGetSymbolAddress((void**)&ap, g_attn);
    cudaGetSymbolAddress((void**)&pp, g_proj);
    cudaGetSymbolAddress((void**)&fp, g_ffh);

    const int M  = BB * NN_;      // 8192 token rows
    const long TOK = (long)M * DD;

    cudaMemcpyAsync(xp, x, TOK * sizeof(float), cudaMemcpyDeviceToDevice);

    // ===== Self-attention block =====
    ln_k<<<M, 256>>>(xp, ln1w, ln1b, hp);
    gemm_nn(hp, wq1, qp, M, DD, DD, DD, DD, DD, nullptr, nullptr);
    gemm_nn(hp, wk1, kp, M, DD, DD, DD, DD, DD, nullptr, nullptr);
    gemm_nn(hp, wv1, vp, M, DD, DD, DD, DD, DD, nullptr, nullptr);
    {
        dim3 grid(NN_ / FBM, BB * HH);
        flash_k<<<grid, 256>>>(qp, kp, vp, ap);
    }
    gemm_nn(ap, wo1, xp, M, DD, DD, DD, DD, DD, bo1, xp);

    // ===== Cross-attention block =====
    ln_k<<<M, 256>>>(xp, ln2w, ln2b, hp);
    gemm_nn(hp, wq2, qp, M, DD, DD, DD, DD, DD, nullptr, nullptr);
    gemm_nn(ctx, wk2, kp, BB * CN_, DD, CDIM, CDIM, DD, DD, nullptr, nullptr);
    gemm_nn(ctx, wv2, vp, BB * CN_, DD, CDIM, CDIM, DD, DD, nullptr, nullptr);
    xattn_k<<<BB * HH * NN_ / 8, 256>>>(qp, kp, vp, ap);
    gemm_nn(ap, wo2, xp, M, DD, DD, DD, DD, DD, bo2, xp);

    // ===== GEGLU feed-forward =====
    ln_k<<<M, 256>>>(xp, ln3w, ln3b, hp);
    gemm_nn(hp, wff1, pp, M, 2 * FF_, DD, DD, 2 * FF_, 2 * FF_, bff1, nullptr);
    {
        const long total = (long)M * FF_;
        geglu_k<<<(int)((total + 255) / 256), 256>>>(pp, fp);
    }
    gemm_nn(fp, wff2, out, M, DD, FF_, FF_, DD, DD, bff2, xp);
}

// round 3
// speedup vs baseline: 1.6620x; 1.6620x over previous
#include <cuda_runtime.h>
#include <cuda_bf16.h>
#include <math.h>
#include <stdint.h>

// ---------------------------------------------------------------------------
// Problem constants
// ---------------------------------------------------------------------------
#define BB   2
#define NN_  4096
#define DD   640
#define HH   8
#define DH   80
#define CN_  77
#define CDIM 768
#define FF_  2560
#define EPS_ 1e-5f
#define SCALE_ATTN 0.11180339887498948f   // 80^-0.5

// ---------------------------------------------------------------------------
// Device scratch (static allocation — no cudaMalloc allowed). ~370 MB total.
// ---------------------------------------------------------------------------
__device__ float g_x   [(size_t)BB * NN_ * DD];
__device__ float g_h   [(size_t)BB * NN_ * DD];
__device__ float g_q   [(size_t)BB * NN_ * DD];
__device__ float g_k   [(size_t)BB * NN_ * DD];
__device__ float g_v   [(size_t)BB * NN_ * DD];
__device__ float g_attn[(size_t)BB * NN_ * DD];
__device__ float g_proj[(size_t)BB * NN_ * 2 * FF_];
__device__ float g_ffh [(size_t)BB * NN_ * FF_];

// ---------------------------------------------------------------------------
// TF32 helpers
// ---------------------------------------------------------------------------
__device__ __forceinline__ uint32_t f2tf32(float v) {
    uint32_t u;
    asm("cvt.rna.tf32.f32 %0, %1;" : "=r"(u) : "f"(v));
    return u;
}

__device__ __forceinline__ void mma_tf32(float* c, const uint32_t* a, const uint32_t* b) {
    asm volatile(
        "mma.sync.aligned.m16n8k8.row.col.f32.tf32.tf32.f32 "
        "{%0,%1,%2,%3}, {%4,%5,%6,%7}, {%8,%9}, {%0,%1,%2,%3};\n"
        : "+f"(c[0]), "+f"(c[1]), "+f"(c[2]), "+f"(c[3])
        : "r"(a[0]), "r"(a[1]), "r"(a[2]), "r"(a[3]),
          "r"(b[0]), "r"(b[1]));
}

// ---------------------------------------------------------------------------
// TF32 tensor-core GEMM: C = A @ B (+bias) (+resid)
//   A row-major [M,K] lda;  B row-major [K,N] ldb.
//   Requirements: K % 16 == 0, N % 128 == 0.  M arbitrary (guarded).
//   Block 128x128x16, 256 threads, 8 warps (4m x 2n), warp tile 32x64.
// ---------------------------------------------------------------------------
#define GPAD 4

__global__ __launch_bounds__(256, 2)
void gemm_tf32_k(const float* __restrict__ A, const float* __restrict__ B,
                 float* __restrict__ C,
                 int M, int N, int K, int lda, int ldb, int ldc,
                 const float* __restrict__ bias,
                 const float* __restrict__ resid)
{
    __shared__ uint32_t As[16][128 + GPAD];   // [k][m]
    __shared__ uint32_t Bs[16][128 + GPAD];   // [k][n]

    const int tid  = threadIdx.x;
    const int wid  = tid >> 5;
    const int lane = tid & 31;
    const int g    = lane >> 2;          // group (0..7)
    const int tg   = lane & 3;           // thread-in-group (0..3)
    const int wm   = wid & 3;            // warp m index (0..3)
    const int wn   = wid >> 2;           // warp n index (0..1)
    const int m0   = blockIdx.y * 128;
    const int n0   = blockIdx.x * 128;

    // ---- tile-load thread mapping ----
    const int arow = tid >> 2;           // 0..63
    const int acol = (tid & 3) * 4;      // 0,4,8,12
    const int brow = tid >> 5;           // 0..7
    const int bcol = (tid & 31) * 4;     // 0..124

    float acc[2][8][4];
    #pragma unroll
    for (int i = 0; i < 2; i++)
        #pragma unroll
        for (int j = 0; j < 8; j++)
            #pragma unroll
            for (int q = 0; q < 4; q++) acc[i][j][q] = 0.f;

    float ra[8], rb[8];

    // ---- prefetch tile 0 ----
    {
        const float4 z4 = make_float4(0.f, 0.f, 0.f, 0.f);
        float4 v;
        v = (m0 + arow      < M) ? *(const float4*)(A + (long)(m0 + arow     ) * lda + acol) : z4;
        ra[0]=v.x; ra[1]=v.y; ra[2]=v.z; ra[3]=v.w;
        v = (m0 + arow + 64 < M) ? *(const float4*)(A + (long)(m0 + arow + 64) * lda + acol) : z4;
        ra[4]=v.x; ra[5]=v.y; ra[6]=v.z; ra[7]=v.w;
        v = *(const float4*)(B + (long)brow       * ldb + n0 + bcol);
        rb[0]=v.x; rb[1]=v.y; rb[2]=v.z; rb[3]=v.w;
        v = *(const float4*)(B + (long)(brow + 8) * ldb + n0 + bcol);
        rb[4]=v.x; rb[5]=v.y; rb[6]=v.z; rb[7]=v.w;
    }

    for (int k0 = 0; k0 < K; k0 += 16) {
        __syncthreads();
        // ---- store prefetched tile to smem (cvt to tf32) ----
        #pragma unroll
        for (int j = 0; j < 4; j++) {
            As[acol + j][arow]      = f2tf32(ra[j]);
            As[acol + j][arow + 64] = f2tf32(ra[4 + j]);
        }
        {
            uint4 b0 = make_uint4(f2tf32(rb[0]), f2tf32(rb[1]), f2tf32(rb[2]), f2tf32(rb[3]));
            uint4 b1 = make_uint4(f2tf32(rb[4]), f2tf32(rb[5]), f2tf32(rb[6]), f2tf32(rb[7]));
            *(uint4*)&Bs[brow][bcol]     = b0;
            *(uint4*)&Bs[brow + 8][bcol] = b1;
        }
        __syncthreads();

        // ---- prefetch next tile (overlaps with MMA below) ----
        if (k0 + 16 < K) {
            const int kn = k0 + 16;
            const float4 z4 = make_float4(0.f, 0.f, 0.f, 0.f);
            float4 v;
            v = (m0 + arow      < M) ? *(const float4*)(A + (long)(m0 + arow     ) * lda + kn + acol) : z4;
            ra[0]=v.x; ra[1]=v.y; ra[2]=v.z; ra[3]=v.w;
            v = (m0 + arow + 64 < M) ? *(const float4*)(A + (long)(m0 + arow + 64) * lda + kn + acol) : z4;
            ra[4]=v.x; ra[5]=v.y; ra[6]=v.z; ra[7]=v.w;
            v = *(const float4*)(B + (long)(kn + brow    ) * ldb + n0 + bcol);
            rb[0]=v.x; rb[1]=v.y; rb[2]=v.z; rb[3]=v.w;
            v = *(const float4*)(B + (long)(kn + brow + 8) * ldb + n0 + bcol);
            rb[4]=v.x; rb[5]=v.y; rb[6]=v.z; rb[7]=v.w;
        }

        // ---- compute 128x128x16 ----
        #pragma unroll
        for (int kk = 0; kk < 16; kk += 8) {
            uint32_t af[2][4], bf[8][2];
            #pragma unroll
            for (int mf = 0; mf < 2; mf++) {
                const int rm = wm * 32 + mf * 16 + g;
                af[mf][0] = As[kk + tg    ][rm];
                af[mf][1] = As[kk + tg    ][rm + 8];
                af[mf][2] = As[kk + tg + 4][rm];
                af[mf][3] = As[kk + tg + 4][rm + 8];
            }
            #pragma unroll
            for (int nf = 0; nf < 8; nf++) {
                const int cb = wn * 64 + nf * 8 + g;
                bf[nf][0] = Bs[kk + tg    ][cb];
                bf[nf][1] = Bs[kk + tg + 4][cb];
            }
            #pragma unroll
            for (int mf = 0; mf < 2; mf++)
                #pragma unroll
                for (int nf = 0; nf < 8; nf++)
                    mma_tf32(acc[mf][nf], af[mf], bf[nf]);
        }
    }

    // ---- epilogue ----
    #pragma unroll
    for (int mf = 0; mf < 2; mf++) {
        const int r0 = m0 + wm * 32 + mf * 16 + g;
        const int r1 = r0 + 8;
        #pragma unroll
        for (int nf = 0; nf < 8; nf++) {
            const int cc = n0 + wn * 64 + nf * 8 + tg * 2;
            float b0 = 0.f, b1 = 0.f;
            if (bias) { b0 = bias[cc]; b1 = bias[cc + 1]; }
            if (r0 < M) {
                float v0 = acc[mf][nf][0] + b0;
                float v1 = acc[mf][nf][1] + b1;
                if (resid) {
                    v0 += resid[(long)r0 * ldc + cc];
                    v1 += resid[(long)r0 * ldc + cc + 1];
                }
                *(float2*)(C + (long)r0 * ldc + cc) = make_float2(v0, v1);
            }
            if (r1 < M) {
                float v0 = acc[mf][nf][2] + b0;
                float v1 = acc[mf][nf][3] + b1;
                if (resid) {
                    v0 += resid[(long)r1 * ldc + cc];
                    v1 += resid[(long)r1 * ldc + cc + 1];
                }
                *(float2*)(C + (long)r1 * ldc + cc) = make_float2(v0, v1);
            }
        }
    }
}

// ---------------------------------------------------------------------------
// Fused flash self-attention (fp32, online softmax). Unchanged from round 2.
// ---------------------------------------------------------------------------
#define FBM 64
#define FBN 32

__global__ __launch_bounds__(256)
void flash_k(const float* __restrict__ Q, const float* __restrict__ K,
             const float* __restrict__ V, float* __restrict__ O)
{
    __shared__ float Qs [FBM][DH + 1];
    __shared__ float KVs[FBN][DH + 1];
    __shared__ float Ps [FBM][FBN + 1];

    const int tid = threadIdx.x;
    const int tx  = tid % 16;
    const int ty  = tid / 16;
    const int bh  = blockIdx.y;
    const int b   = bh / HH, h = bh % HH;
    const int row0 = blockIdx.x * FBM;

    const float* Qp = Q + (long)b * NN_ * DD + h * DH;
    const float* Kp = K + (long)b * NN_ * DD + h * DH;
    const float* Vp = V + (long)b * NN_ * DD + h * DH;
    float*       Op = O + (long)b * NN_ * DD + h * DH;

    for (int idx = tid; idx < FBM * (DH / 4); idx += 256) {
        int r = idx / (DH / 4), c = idx % (DH / 4);
        float4 v = *(const float4*)(Qp + (long)(row0 + r) * DD + c * 4);
        Qs[r][c * 4 + 0] = v.x; Qs[r][c * 4 + 1] = v.y;
        Qs[r][c * 4 + 2] = v.z; Qs[r][c * 4 + 3] = v.w;
    }

    float m[4], l[4], acc[4][5];
    #pragma unroll
    for (int i = 0; i < 4; i++) {
        m[i] = -1e30f; l[i] = 0.f;
        #pragma unroll
        for (int j = 0; j < 5; j++) acc[i][j] = 0.f;
    }

    for (int kt = 0; kt < NN_ / FBN; kt++) {
        __syncthreads();
        for (int idx = tid; idx < FBN * (DH / 4); idx += 256) {
            int r = idx / (DH / 4), c = idx % (DH / 4);
            float4 v = *(const float4*)(Kp + (long)(kt * FBN + r) * DD + c * 4);
            KVs[r][c * 4 + 0] = v.x; KVs[r][c * 4 + 1] = v.y;
            KVs[r][c * 4 + 2] = v.z; KVs[r][c * 4 + 3] = v.w;
        }
        __syncthreads();

        float s[4][2];
        #pragma unroll
        for (int i = 0; i < 4; i++) { s[i][0] = 0.f; s[i][1] = 0.f; }
        #pragma unroll 4
        for (int d = 0; d < DH; d++) {
            float a0 = Qs[ty * 4 + 0][d];
            float a1 = Qs[ty * 4 + 1][d];
            float a2 = Qs[ty * 4 + 2][d];
            float a3 = Qs[ty * 4 + 3][d];
            float b0 = KVs[tx * 2 + 0][d];
            float b1 = KVs[tx * 2 + 1][d];
            s[0][0] += a0 * b0; s[0][1] += a0 * b1;
            s[1][0] += a1 * b0; s[1][1] += a1 * b1;
            s[2][0] += a2 * b0; s[2][1] += a2 * b1;
            s[3][0] += a3 * b0; s[3][1] += a3 * b1;
        }

        #pragma unroll
        for (int i = 0; i < 4; i++) {
            float rm = fmaxf(s[i][0], s[i][1]) * SCALE_ATTN;
            #pragma unroll
            for (int o = 8; o > 0; o >>= 1)
                rm = fmaxf(rm, __shfl_xor_sync(0xffffffffu, rm, o));
            float mn = fmaxf(m[i], rm);
            float corr = __expf(m[i] - mn);
            float p0 = __expf(s[i][0] * SCALE_ATTN - mn);
            float p1 = __expf(s[i][1] * SCALE_ATTN - mn);
            float rs = p0 + p1;
            #pragma unroll
            for (int o = 8; o > 0; o >>= 1)
                rs += __shfl_xor_sync(0xffffffffu, rs, o);
            l[i] = l[i] * corr + rs;
            m[i] = mn;
            #pragma unroll
            for (int j = 0; j < 5; j++) acc[i][j] *= corr;
            Ps[ty * 4 + i][tx * 2 + 0] = p0;
            Ps[ty * 4 + i][tx * 2 + 1] = p1;
        }
        __syncthreads();

        for (int idx = tid; idx < FBN * (DH / 4); idx += 256) {
            int r = idx / (DH / 4), c = idx % (DH / 4);
            float4 v = *(const float4*)(Vp + (long)(kt * FBN + r) * DD + c * 4);
            KVs[r][c * 4 + 0] = v.x; KVs[r][c * 4 + 1] = v.y;
            KVs[r][c * 4 + 2] = v.z; KVs[r][c * 4 + 3] = v.w;
        }
        __syncthreads();

        #pragma unroll 4
        for (int kk = 0; kk < FBN; kk++) {
            float p0 = Ps[ty * 4 + 0][kk];
            float p1 = Ps[ty * 4 + 1][kk];
            float p2 = Ps[ty * 4 + 2][kk];
            float p3 = Ps[ty * 4 + 3][kk];
            #pragma unroll
            for (int j = 0; j < 5; j++) {
                float vv = KVs[kk][tx * 5 + j];
                acc[0][j] += p0 * vv;
                acc[1][j] += p1 * vv;
                acc[2][j] += p2 * vv;
                acc[3][j] += p3 * vv;
            }
        }
    }

    #pragma unroll
    for (int i = 0; i < 4; i++) {
        float inv = 1.f / l[i];
        #pragma unroll
        for (int j = 0; j < 5; j++)
            Op[(long)(row0 + ty * 4 + i) * DD + tx * 5 + j] = acc[i][j] * inv;
    }
}

// ---------------------------------------------------------------------------
// LayerNorm
// ---------------------------------------------------------------------------
__global__ void ln_k(const float* __restrict__ x, const float* __restrict__ w,
                     const float* __restrict__ b, float* __restrict__ out)
{
    __shared__ float red[256];
    __shared__ float red2[256];
    const long row = blockIdx.x;
    const float* p = x + row * DD;
    float s = 0.f, ss = 0.f;
    float lv[3];
    int cnt = 0;
    for (int idx = threadIdx.x; idx < DD; idx += 256) {
        float v = p[idx];
        lv[cnt++] = v;
        s += v; ss += v * v;
    }
    red[threadIdx.x] = s; red2[threadIdx.x] = ss;
    __syncthreads();
    for (int st = 128; st > 0; st >>= 1) {
        if (threadIdx.x < st) {
            red[threadIdx.x]  += red[threadIdx.x + st];
            red2[threadIdx.x] += red2[threadIdx.x + st];
        }
        __syncthreads();
    }
    const float mean = red[0] * (1.f / DD);
    const float var  = red2[0] * (1.f / DD) - mean * mean;
    const float inv  = rsqrtf(var + EPS_);
    float* o = out + row * DD;
    cnt = 0;
    for (int idx = threadIdx.x; idx < DD; idx += 256) {
        o[idx] = (lv[cnt++] - mean) * inv * w[idx] + b[idx];
    }
}

// ---------------------------------------------------------------------------
// Fused cross-attention: 77 keys, one warp per query row.
// ---------------------------------------------------------------------------
__global__ void xattn_k(const float* __restrict__ Q, const float* __restrict__ K,
                        const float* __restrict__ V, float* __restrict__ O)
{
    __shared__ float qbuf[8][DH];
    __shared__ float sc[8][80];
    const int wid  = threadIdx.x >> 5;
    const int lane = threadIdx.x & 31;
    const long wg  = (long)blockIdx.x * 8 + wid;
    const int q  = (int)(wg % NN_);
    const int bh = (int)(wg / NN_);
    const int h  = bh % HH;
    const int b  = bh / HH;

    const float* qp = Q + ((long)(b * NN_ + q) * DD + h * DH);
    for (int d = lane; d < DH; d += 32) qbuf[wid][d] = qp[d];
    __syncwarp();

    float mx = -1e30f;
    for (int j = lane; j < CN_; j += 32) {
        const float* kp = K + ((long)(b * CN_ + j) * DD + h * DH);
        float s = 0.f;
        #pragma unroll
        for (int d = 0; d < DH; d++) s += qbuf[wid][d] * kp[d];
        s *= SCALE_ATTN;
        sc[wid][j] = s;
        mx = fmaxf(mx, s);
    }
    #pragma unroll
    for (int o = 16; o > 0; o >>= 1) mx = fmaxf(mx, __shfl_xor_sync(0xffffffff, mx, o));

    float sum = 0.f;
    __syncwarp();
    for (int j = lane; j < CN_; j += 32) {
        float e = __expf(sc[wid][j] - mx);
        sc[wid][j] = e;
        sum += e;
    }
    #pragma unroll
    for (int o = 16; o > 0; o >>= 1) sum += __shfl_xor_sync(0xffffffff, sum, o);
    const float inv = 1.f / sum;
    __syncwarp();

    float* op = O + ((long)(b * NN_ + q) * DD + h * DH);
    for (int d = lane; d < DH; d += 32) {
        float acc = 0.f;
        #pragma unroll 7
        for (int j = 0; j < CN_; j++)
            acc += sc[wid][j] * V[(long)(b * CN_ + j) * DD + h * DH + d];
        op[d] = acc * inv;
    }
}

// ---------------------------------------------------------------------------
// GEGLU
// ---------------------------------------------------------------------------
__global__ void geglu_k(const float* __restrict__ proj, float* __restrict__ out)
{
    const long idx = (long)blockIdx.x * blockDim.x + threadIdx.x;
    const long total = (long)BB * NN_ * FF_;
    if (idx >= total) return;
    const long row = idx / FF_;
    const long col = idx % FF_;
    const float a = proj[row * (2 * FF_) + col];
    const float g = proj[row * (2 * FF_) + FF_ + col];
    const float gelu = 0.5f * g * (1.f + erff(g * 0.70710678118654752f));
    out[row * FF_ + col] = a * gelu;
}

// ---------------------------------------------------------------------------
// Host-side launch helpers
// ---------------------------------------------------------------------------
static inline void gemm_nn(const float* A, const float* B, float* C,
                           int M, int N, int K, int lda, int ldb, int ldc,
                           const float* bias, const float* resid)
{
    dim3 grid(N / 128, (M + 127) / 128, 1);
    gemm_tf32_k<<<grid, 256>>>(A, B, C, M, N, K, lda, ldb, ldc, bias, resid);
}

extern "C" void kernel_launch(void* const* d_in, const int* in_sizes, int n_in,
                              void* d_out, int out_size)
{
    const float* x      = (const float*)d_in[0];
    const float* ctx    = (const float*)d_in[1];
    const float* ln1w   = (const float*)d_in[2];
    const float* ln1b   = (const float*)d_in[3];
    const float* ln2w   = (const float*)d_in[4];
    const float* ln2b   = (const float*)d_in[5];
    const float* ln3w   = (const float*)d_in[6];
    const float* ln3b   = (const float*)d_in[7];
    const float* wq1    = (const float*)d_in[8];
    const float* wk1    = (const float*)d_in[9];
    const float* wv1    = (const float*)d_in[10];
    const float* wo1    = (const float*)d_in[11];
    const float* bo1    = (const float*)d_in[12];
    const float* wq2    = (const float*)d_in[13];
    const float* wk2    = (const float*)d_in[14];
    const float* wv2    = (const float*)d_in[15];
    const float* wo2    = (const float*)d_in[16];
    const float* bo2    = (const float*)d_in[17];
    const float* wff1   = (const float*)d_in[18];
    const float* bff1   = (const float*)d_in[19];
    const float* wff2   = (const float*)d_in[20];
    const float* bff2   = (const float*)d_in[21];
    float* out = (float*)d_out;

    float *xp, *hp, *qp, *kp, *vp, *ap, *pp, *fp;
    cudaGetSymbolAddress((void**)&xp, g_x);
    cudaGetSymbolAddress((void**)&hp, g_h);
    cudaGetSymbolAddress((void**)&qp, g_q);
    cudaGetSymbolAddress((void**)&kp, g_k);
    cudaGetSymbolAddress((void**)&vp, g_v);
    cudaGetSymbolAddress((void**)&ap, g_attn);
    cudaGetSymbolAddress((void**)&pp, g_proj);
    cudaGetSymbolAddress((void**)&fp, g_ffh);

    const int M  = BB * NN_;      // 8192 token rows
    const long TOK = (long)M * DD;

    cudaMemcpyAsync(xp, x, TOK * sizeof(float), cudaMemcpyDeviceToDevice);

    // ===== Self-attention block =====
    ln_k<<<M, 256>>>(xp, ln1w, ln1b, hp);
    gemm_nn(hp, wq1, qp, M, DD, DD, DD, DD, DD, nullptr, nullptr);
    gemm_nn(hp, wk1, kp, M, DD, DD, DD, DD, DD, nullptr, nullptr);
    gemm_nn(hp, wv1, vp, M, DD, DD, DD, DD, DD, nullptr, nullptr);
    {
        dim3 grid(NN_ / FBM, BB * HH);
        flash_k<<<grid, 256>>>(qp, kp, vp, ap);
    }
    gemm_nn(ap, wo1, xp, M, DD, DD, DD, DD, DD, bo1, xp);

    // ===== Cross-attention block =====
    ln_k<<<M, 256>>>(xp, ln2w, ln2b, hp);
    gemm_nn(hp, wq2, qp, M, DD, DD, DD, DD, DD, nullptr, nullptr);
    gemm_nn(ctx, wk2, kp, BB * CN_, DD, CDIM, CDIM, DD, DD, nullptr, nullptr);
    gemm_nn(ctx, wv2, vp, BB * CN_, DD, CDIM, CDIM, DD, DD, nullptr, nullptr);
    xattn_k<<<BB * HH * NN_ / 8, 256>>>(qp, kp, vp, ap);
    gemm_nn(ap, wo2, xp, M, DD, DD, DD, DD, DD, bo2, xp);

    // ===== GEGLU feed-forward =====
    ln_k<<<M, 256>>>(xp, ln3w, ln3b, hp);
    gemm_nn(hp, wff1, pp, M, 2 * FF_, DD, DD, 2 * FF_, 2 * FF_, bff1, nullptr);
    {
        const long total = (long)M * FF_;
        geglu_k<<<(int)((total + 255) / 256), 256>>>(pp, fp);
    }
    gemm_nn(fp, wff2, out, M, DD, FF_, FF_, DD, DD, bff2, xp);
}

// round 4
// speedup vs baseline: 2.6015x; 1.5652x over previous
#include <cuda_runtime.h>
#include <cuda_bf16.h>
#include <math.h>
#include <stdint.h>

// ---------------------------------------------------------------------------
// Problem constants
// ---------------------------------------------------------------------------
#define BB   2
#define NN_  4096
#define DD   640
#define HH   8
#define DH   80
#define CN_  77
#define CDIM 768
#define FF_  2560
#define EPS_ 1e-5f
#define SCALE_ATTN 0.11180339887498948f   // 80^-0.5

// ---------------------------------------------------------------------------
// Device scratch (static allocation — no cudaMalloc allowed). ~370 MB total.
// ---------------------------------------------------------------------------
__device__ float g_x   [(size_t)BB * NN_ * DD];
__device__ float g_h   [(size_t)BB * NN_ * DD];
__device__ float g_q   [(size_t)BB * NN_ * DD];
__device__ float g_k   [(size_t)BB * NN_ * DD];
__device__ float g_v   [(size_t)BB * NN_ * DD];
__device__ float g_attn[(size_t)BB * NN_ * DD];
__device__ float g_proj[(size_t)BB * NN_ * 2 * FF_];
__device__ float g_ffh [(size_t)BB * NN_ * FF_];

// ---------------------------------------------------------------------------
// TF32 helpers
// ---------------------------------------------------------------------------
__device__ __forceinline__ uint32_t f2tf32(float v) {
    uint32_t u;
    asm("cvt.rna.tf32.f32 %0, %1;" : "=r"(u) : "f"(v));
    return u;
}

__device__ __forceinline__ void mma_tf32(float* c, const uint32_t* a, const uint32_t* b) {
    asm volatile(
        "mma.sync.aligned.m16n8k8.row.col.f32.tf32.tf32.f32 "
        "{%0,%1,%2,%3}, {%4,%5,%6,%7}, {%8,%9}, {%0,%1,%2,%3};\n"
        : "+f"(c[0]), "+f"(c[1]), "+f"(c[2]), "+f"(c[3])
        : "r"(a[0]), "r"(a[1]), "r"(a[2]), "r"(a[3]),
          "r"(b[0]), "r"(b[1]));
}

__device__ __forceinline__ void cp16(uint32_t smem_addr, const void* gptr) {
    asm volatile("cp.async.ca.shared.global [%0], [%1], 16;\n"
                 :: "r"(smem_addr), "l"(gptr));
}

// ---------------------------------------------------------------------------
// TF32 tensor-core GEMM: C = A @ B (+bias) (+resid)   (unchanged from R3)
// ---------------------------------------------------------------------------
#define GPAD 4

__global__ __launch_bounds__(256, 2)
void gemm_tf32_k(const float* __restrict__ A, const float* __restrict__ B,
                 float* __restrict__ C,
                 int M, int N, int K, int lda, int ldb, int ldc,
                 const float* __restrict__ bias,
                 const float* __restrict__ resid)
{
    __shared__ uint32_t As[16][128 + GPAD];
    __shared__ uint32_t Bs[16][128 + GPAD];

    const int tid  = threadIdx.x;
    const int wid  = tid >> 5;
    const int lane = tid & 31;
    const int g    = lane >> 2;
    const int tg   = lane & 3;
    const int wm   = wid & 3;
    const int wn   = wid >> 2;
    const int m0   = blockIdx.y * 128;
    const int n0   = blockIdx.x * 128;

    const int arow = tid >> 2;
    const int acol = (tid & 3) * 4;
    const int brow = tid >> 5;
    const int bcol = (tid & 31) * 4;

    float acc[2][8][4];
    #pragma unroll
    for (int i = 0; i < 2; i++)
        #pragma unroll
        for (int j = 0; j < 8; j++)
            #pragma unroll
            for (int q = 0; q < 4; q++) acc[i][j][q] = 0.f;

    float ra[8], rb[8];

    {
        const float4 z4 = make_float4(0.f, 0.f, 0.f, 0.f);
        float4 v;
        v = (m0 + arow      < M) ? *(const float4*)(A + (long)(m0 + arow     ) * lda + acol) : z4;
        ra[0]=v.x; ra[1]=v.y; ra[2]=v.z; ra[3]=v.w;
        v = (m0 + arow + 64 < M) ? *(const float4*)(A + (long)(m0 + arow + 64) * lda + acol) : z4;
        ra[4]=v.x; ra[5]=v.y; ra[6]=v.z; ra[7]=v.w;
        v = *(const float4*)(B + (long)brow       * ldb + n0 + bcol);
        rb[0]=v.x; rb[1]=v.y; rb[2]=v.z; rb[3]=v.w;
        v = *(const float4*)(B + (long)(brow + 8) * ldb + n0 + bcol);
        rb[4]=v.x; rb[5]=v.y; rb[6]=v.z; rb[7]=v.w;
    }

    for (int k0 = 0; k0 < K; k0 += 16) {
        __syncthreads();
        #pragma unroll
        for (int j = 0; j < 4; j++) {
            As[acol + j][arow]      = f2tf32(ra[j]);
            As[acol + j][arow + 64] = f2tf32(ra[4 + j]);
        }
        {
            uint4 b0 = make_uint4(f2tf32(rb[0]), f2tf32(rb[1]), f2tf32(rb[2]), f2tf32(rb[3]));
            uint4 b1 = make_uint4(f2tf32(rb[4]), f2tf32(rb[5]), f2tf32(rb[6]), f2tf32(rb[7]));
            *(uint4*)&Bs[brow][bcol]     = b0;
            *(uint4*)&Bs[brow + 8][bcol] = b1;
        }
        __syncthreads();

        if (k0 + 16 < K) {
            const int kn = k0 + 16;
            const float4 z4 = make_float4(0.f, 0.f, 0.f, 0.f);
            float4 v;
            v = (m0 + arow      < M) ? *(const float4*)(A + (long)(m0 + arow     ) * lda + kn + acol) : z4;
            ra[0]=v.x; ra[1]=v.y; ra[2]=v.z; ra[3]=v.w;
            v = (m0 + arow + 64 < M) ? *(const float4*)(A + (long)(m0 + arow + 64) * lda + kn + acol) : z4;
            ra[4]=v.x; ra[5]=v.y; ra[6]=v.z; ra[7]=v.w;
            v = *(const float4*)(B + (long)(kn + brow    ) * ldb + n0 + bcol);
            rb[0]=v.x; rb[1]=v.y; rb[2]=v.z; rb[3]=v.w;
            v = *(const float4*)(B + (long)(kn + brow + 8) * ldb + n0 + bcol);
            rb[4]=v.x; rb[5]=v.y; rb[6]=v.z; rb[7]=v.w;
        }

        #pragma unroll
        for (int kk = 0; kk < 16; kk += 8) {
            uint32_t af[2][4], bf[8][2];
            #pragma unroll
            for (int mf = 0; mf < 2; mf++) {
                const int rm = wm * 32 + mf * 16 + g;
                af[mf][0] = As[kk + tg    ][rm];
                af[mf][1] = As[kk + tg    ][rm + 8];
                af[mf][2] = As[kk + tg + 4][rm];
                af[mf][3] = As[kk + tg + 4][rm + 8];
            }
            #pragma unroll
            for (int nf = 0; nf < 8; nf++) {
                const int cb = wn * 64 + nf * 8 + g;
                bf[nf][0] = Bs[kk + tg    ][cb];
                bf[nf][1] = Bs[kk + tg + 4][cb];
            }
            #pragma unroll
            for (int mf = 0; mf < 2; mf++)
                #pragma unroll
                for (int nf = 0; nf < 8; nf++)
                    mma_tf32(acc[mf][nf], af[mf], bf[nf]);
        }
    }

    #pragma unroll
    for (int mf = 0; mf < 2; mf++) {
        const int r0 = m0 + wm * 32 + mf * 16 + g;
        const int r1 = r0 + 8;
        #pragma unroll
        for (int nf = 0; nf < 8; nf++) {
            const int cc = n0 + wn * 64 + nf * 8 + tg * 2;
            float b0 = 0.f, b1 = 0.f;
            if (bias) { b0 = bias[cc]; b1 = bias[cc + 1]; }
            if (r0 < M) {
                float v0 = acc[mf][nf][0] + b0;
                float v1 = acc[mf][nf][1] + b1;
                if (resid) {
                    v0 += resid[(long)r0 * ldc + cc];
                    v1 += resid[(long)r0 * ldc + cc + 1];
                }
                *(float2*)(C + (long)r0 * ldc + cc) = make_float2(v0, v1);
            }
            if (r1 < M) {
                float v0 = acc[mf][nf][2] + b0;
                float v1 = acc[mf][nf][3] + b1;
                if (resid) {
                    v0 += resid[(long)r1 * ldc + cc];
                    v1 += resid[(long)r1 * ldc + cc + 1];
                }
                *(float2*)(C + (long)r1 * ldc + cc) = make_float2(v0, v1);
            }
        }
    }
}

// ---------------------------------------------------------------------------
// TF32 tensor-core flash attention.
//   Block: 128 queries (8 warps x 16 rows) x full head; key tiles of 64.
//   cp.async double-buffered K/V tiles; online softmax in registers.
//   Dynamic smem layout (uint32 words):
//     Ks[2][64*84]  @ 0      (5376 words/buf)
//     Vs[2][64*88]  @ 10752  (5632 words/buf)
//     Ps[128*68]    @ 22016
//   total 30720 words = 122880 bytes
// ---------------------------------------------------------------------------
#define TBM 128
#define TBN 64
#define KST 84
#define VST 88
#define PST 68
#define FTC_SMEM 122880

__global__ void __launch_bounds__(256)
flash_tc_k(const float* __restrict__ Q, const float* __restrict__ K,
           const float* __restrict__ V, float* __restrict__ O)
{
    extern __shared__ uint32_t fsm[];
    uint32_t* Ps = fsm + 22016;

    const int tid  = threadIdx.x;
    const int wid  = tid >> 5;
    const int lane = tid & 31;
    const int g    = lane >> 2;
    const int tg   = lane & 3;
    const int bh   = blockIdx.y;
    const int b    = bh / HH, h = bh % HH;
    const int row0 = blockIdx.x * TBM;
    const int NT   = NN_ / TBN;   // 64 key tiles

    const float* Qp = Q + (long)(b * NN_ + row0) * DD + h * DH;
    const float* Kp = K + (long)b * NN_ * DD + h * DH;
    const float* Vp = V + (long)b * NN_ * DD + h * DH;
    float*       Op = O + (long)(b * NN_ + row0) * DD + h * DH;

    const uint32_t sb = (uint32_t)__cvta_generic_to_shared(fsm);

    // ---- Q fragments (persistent, RNA tf32) ----
    uint32_t qa[10][4];
    {
        const float* qw = Qp + (long)(wid * 16) * DD;
        #pragma unroll
        for (int kc = 0; kc < 10; kc++) {
            const int c0 = kc * 8 + tg;
            qa[kc][0] = f2tf32(qw[(long)g       * DD + c0]);
            qa[kc][1] = f2tf32(qw[(long)(g + 8) * DD + c0]);
            qa[kc][2] = f2tf32(qw[(long)g       * DD + c0 + 4]);
            qa[kc][3] = f2tf32(qw[(long)(g + 8) * DD + c0 + 4]);
        }
    }

    float oa[10][4];
    #pragma unroll
    for (int nf = 0; nf < 10; nf++)
        #pragma unroll
        for (int q = 0; q < 4; q++) oa[nf][q] = 0.f;
    float mr0 = -1e30f, mr1 = -1e30f, lr0 = 0.f, lr1 = 0.f;

    // ---- issue cp.async loads of K/V tile kt into buffer `buf` ----
    #define ISSUE_TILE(kt, buf)                                                          \
    {                                                                                     \
        _Pragma("unroll")                                                                 \
        for (int i = 0; i < 5; i++) {                                                     \
            const int idx = i * 256 + tid;                                                \
            const int r = idx / 20, c = idx % 20;                                         \
            cp16(sb + (uint32_t)((buf) * 5376 + r * KST + c * 4) * 4u,                    \
                 Kp + (long)((kt) * TBN + r) * DD + c * 4);                               \
        }                                                                                 \
        _Pragma("unroll")                                                                 \
        for (int i = 0; i < 5; i++) {                                                     \
            const int idx = i * 256 + tid;                                                \
            const int r = idx / 20, c = idx % 20;                                         \
            cp16(sb + (uint32_t)(10752 + (buf) * 5632 + r * VST + c * 4) * 4u,            \
                 Vp + (long)((kt) * TBN + r) * DD + c * 4);                               \
        }                                                                                 \
        asm volatile("cp.async.commit_group;\n" ::);                                      \
    }

    ISSUE_TILE(0, 0);

    for (int kt = 0; kt < NT; kt++) {
        const int buf = kt & 1;
        __syncthreads();                       // prior compute done before buffer reuse
        if (kt + 1 < NT) {
            ISSUE_TILE(kt + 1, buf ^ 1);
            asm volatile("cp.async.wait_group 1;\n" ::);
        } else {
            asm volatile("cp.async.wait_group 0;\n" ::);
        }
        __syncthreads();                       // tile `buf` visible to all warps

        const uint32_t* Ks = fsm + buf * 5376;
        const uint32_t* Vs = fsm + 10752 + buf * 5632;

        // ---- S = Q @ K^T for this warp's 16 rows ----
        float sa[8][4];
        #pragma unroll
        for (int nf = 0; nf < 8; nf++)
            #pragma unroll
            for (int q = 0; q < 4; q++) sa[nf][q] = 0.f;

        #pragma unroll
        for (int kc = 0; kc < 10; kc++) {
            uint32_t bf[8][2];
            #pragma unroll
            for (int nf = 0; nf < 8; nf++) {
                bf[nf][0] = Ks[(nf * 8 + g) * KST + kc * 8 + tg];
                bf[nf][1] = Ks[(nf * 8 + g) * KST + kc * 8 + tg + 4];
            }
            #pragma unroll
            for (int nf = 0; nf < 8; nf++)
                mma_tf32(sa[nf], qa[kc], bf[nf]);
        }

        // ---- online softmax (rows g and g+8 of this warp tile) ----
        float rm0 = -1e30f, rm1 = -1e30f;
        #pragma unroll
        for (int nf = 0; nf < 8; nf++) {
            rm0 = fmaxf(rm0, fmaxf(sa[nf][0], sa[nf][1]));
            rm1 = fmaxf(rm1, fmaxf(sa[nf][2], sa[nf][3]));
        }
        rm0 *= SCALE_ATTN; rm1 *= SCALE_ATTN;
        rm0 = fmaxf(rm0, __shfl_xor_sync(0xffffffffu, rm0, 1));
        rm0 = fmaxf(rm0, __shfl_xor_sync(0xffffffffu, rm0, 2));
        rm1 = fmaxf(rm1, __shfl_xor_sync(0xffffffffu, rm1, 1));
        rm1 = fmaxf(rm1, __shfl_xor_sync(0xffffffffu, rm1, 2));

        const float mn0 = fmaxf(mr0, rm0);
        const float mn1 = fmaxf(mr1, rm1);
        const float cr0 = __expf(mr0 - mn0);
        const float cr1 = __expf(mr1 - mn1);

        float rs0 = 0.f, rs1 = 0.f;
        uint32_t* Pw0 = Ps + (wid * 16 + g) * PST;
        uint32_t* Pw1 = Ps + (wid * 16 + g + 8) * PST;
        #pragma unroll
        for (int nf = 0; nf < 8; nf++) {
            float p00 = __expf(sa[nf][0] * SCALE_ATTN - mn0);
            float p01 = __expf(sa[nf][1] * SCALE_ATTN - mn0);
            float p10 = __expf(sa[nf][2] * SCALE_ATTN - mn1);
            float p11 = __expf(sa[nf][3] * SCALE_ATTN - mn1);
            rs0 += p00 + p01;
            rs1 += p10 + p11;
            const int cc = nf * 8 + tg * 2;
            Pw0[cc]     = f2tf32(p00);
            Pw0[cc + 1] = f2tf32(p01);
            Pw1[cc]     = f2tf32(p10);
            Pw1[cc + 1] = f2tf32(p11);
        }
        rs0 += __shfl_xor_sync(0xffffffffu, rs0, 1);
        rs0 += __shfl_xor_sync(0xffffffffu, rs0, 2);
        rs1 += __shfl_xor_sync(0xffffffffu, rs1, 1);
        rs1 += __shfl_xor_sync(0xffffffffu, rs1, 2);

        lr0 = lr0 * cr0 + rs0;  mr0 = mn0;
        lr1 = lr1 * cr1 + rs1;  mr1 = mn1;

        #pragma unroll
        for (int nf = 0; nf < 10; nf++) {
            oa[nf][0] *= cr0; oa[nf][1] *= cr0;
            oa[nf][2] *= cr1; oa[nf][3] *= cr1;
        }
        __syncwarp();   // Ps writes visible to own warp

        // ---- O += P @ V ----
        #pragma unroll
        for (int kc = 0; kc < 8; kc++) {
            uint32_t pa[4];
            pa[0] = Ps[(wid * 16 + g)     * PST + kc * 8 + tg];
            pa[1] = Ps[(wid * 16 + g + 8) * PST + kc * 8 + tg];
            pa[2] = Ps[(wid * 16 + g)     * PST + kc * 8 + tg + 4];
            pa[3] = Ps[(wid * 16 + g + 8) * PST + kc * 8 + tg + 4];
            #pragma unroll
            for (int nf = 0; nf < 10; nf++) {
                uint32_t bf[2];
                bf[0] = Vs[(kc * 8 + tg)     * VST + nf * 8 + g];
                bf[1] = Vs[(kc * 8 + tg + 4) * VST + nf * 8 + g];
                mma_tf32(oa[nf], pa, bf);
            }
        }
    }

    // ---- finalize ----
    const float inv0 = 1.f / lr0;
    const float inv1 = 1.f / lr1;
    #pragma unroll
    for (int nf = 0; nf < 10; nf++) {
        const int cc = nf * 8 + tg * 2;
        *(float2*)(Op + (long)(wid * 16 + g)     * DD + cc) =
            make_float2(oa[nf][0] * inv0, oa[nf][1] * inv0);
        *(float2*)(Op + (long)(wid * 16 + g + 8) * DD + cc) =
            make_float2(oa[nf][2] * inv1, oa[nf][3] * inv1);
    }
}

// ---------------------------------------------------------------------------
// LayerNorm
// ---------------------------------------------------------------------------
__global__ void ln_k(const float* __restrict__ x, const float* __restrict__ w,
                     const float* __restrict__ b, float* __restrict__ out)
{
    __shared__ float red[256];
    __shared__ float red2[256];
    const long row = blockIdx.x;
    const float* p = x + row * DD;
    float s = 0.f, ss = 0.f;
    float lv[3];
    int cnt = 0;
    for (int idx = threadIdx.x; idx < DD; idx += 256) {
        float v = p[idx];
        lv[cnt++] = v;
        s += v; ss += v * v;
    }
    red[threadIdx.x] = s; red2[threadIdx.x] = ss;
    __syncthreads();
    for (int st = 128; st > 0; st >>= 1) {
        if (threadIdx.x < st) {
            red[threadIdx.x]  += red[threadIdx.x + st];
            red2[threadIdx.x] += red2[threadIdx.x + st];
        }
        __syncthreads();
    }
    const float mean = red[0] * (1.f / DD);
    const float var  = red2[0] * (1.f / DD) - mean * mean;
    const float inv  = rsqrtf(var + EPS_);
    float* o = out + row * DD;
    cnt = 0;
    for (int idx = threadIdx.x; idx < DD; idx += 256) {
        o[idx] = (lv[cnt++] - mean) * inv * w[idx] + b[idx];
    }
}

// ---------------------------------------------------------------------------
// Fused cross-attention: 77 keys, one warp per query row.
// ---------------------------------------------------------------------------
__global__ void xattn_k(const float* __restrict__ Q, const float* __restrict__ K,
                        const float* __restrict__ V, float* __restrict__ O)
{
    __shared__ float qbuf[8][DH];
    __shared__ float sc[8][80];
    const int wid  = threadIdx.x >> 5;
    const int lane = threadIdx.x & 31;
    const long wg  = (long)blockIdx.x * 8 + wid;
    const int q  = (int)(wg % NN_);
    const int bh = (int)(wg / NN_);
    const int h  = bh % HH;
    const int b  = bh / HH;

    const float* qp = Q + ((long)(b * NN_ + q) * DD + h * DH);
    for (int d = lane; d < DH; d += 32) qbuf[wid][d] = qp[d];
    __syncwarp();

    float mx = -1e30f;
    for (int j = lane; j < CN_; j += 32) {
        const float* kp = K + ((long)(b * CN_ + j) * DD + h * DH);
        float s = 0.f;
        #pragma unroll
        for (int d = 0; d < DH; d++) s += qbuf[wid][d] * kp[d];
        s *= SCALE_ATTN;
        sc[wid][j] = s;
        mx = fmaxf(mx, s);
    }
    #pragma unroll
    for (int o = 16; o > 0; o >>= 1) mx = fmaxf(mx, __shfl_xor_sync(0xffffffff, mx, o));

    float sum = 0.f;
    __syncwarp();
    for (int j = lane; j < CN_; j += 32) {
        float e = __expf(sc[wid][j] - mx);
        sc[wid][j] = e;
        sum += e;
    }
    #pragma unroll
    for (int o = 16; o > 0; o >>= 1) sum += __shfl_xor_sync(0xffffffff, sum, o);
    const float inv = 1.f / sum;
    __syncwarp();

    float* op = O + ((long)(b * NN_ + q) * DD + h * DH);
    for (int d = lane; d < DH; d += 32) {
        float acc = 0.f;
        #pragma unroll 7
        for (int j = 0; j < CN_; j++)
            acc += sc[wid][j] * V[(long)(b * CN_ + j) * DD + h * DH + d];
        op[d] = acc * inv;
    }
}

// ---------------------------------------------------------------------------
// GEGLU
// ---------------------------------------------------------------------------
__global__ void geglu_k(const float* __restrict__ proj, float* __restrict__ out)
{
    const long idx = (long)blockIdx.x * blockDim.x + threadIdx.x;
    const long total = (long)BB * NN_ * FF_;
    if (idx >= total) return;
    const long row = idx / FF_;
    const long col = idx % FF_;
    const float a = proj[row * (2 * FF_) + col];
    const float g = proj[row * (2 * FF_) + FF_ + col];
    const float gelu = 0.5f * g * (1.f + erff(g * 0.70710678118654752f));
    out[row * FF_ + col] = a * gelu;
}

// ---------------------------------------------------------------------------
// Host-side launch helpers
// ---------------------------------------------------------------------------
static inline void gemm_nn(const float* A, const float* B, float* C,
                           int M, int N, int K, int lda, int ldb, int ldc,
                           const float* bias, const float* resid)
{
    dim3 grid(N / 128, (M + 127) / 128, 1);
    gemm_tf32_k<<<grid, 256>>>(A, B, C, M, N, K, lda, ldb, ldc, bias, resid);
}

extern "C" void kernel_launch(void* const* d_in, const int* in_sizes, int n_in,
                              void* d_out, int out_size)
{
    const float* x      = (const float*)d_in[0];
    const float* ctx    = (const float*)d_in[1];
    const float* ln1w   = (const float*)d_in[2];
    const float* ln1b   = (const float*)d_in[3];
    const float* ln2w   = (const float*)d_in[4];
    const float* ln2b   = (const float*)d_in[5];
    const float* ln3w   = (const float*)d_in[6];
    const float* ln3b   = (const float*)d_in[7];
    const float* wq1    = (const float*)d_in[8];
    const float* wk1    = (const float*)d_in[9];
    const float* wv1    = (const float*)d_in[10];
    const float* wo1    = (const float*)d_in[11];
    const float* bo1    = (const float*)d_in[12];
    const float* wq2    = (const float*)d_in[13];
    const float* wk2    = (const float*)d_in[14];
    const float* wv2    = (const float*)d_in[15];
    const float* wo2    = (const float*)d_in[16];
    const float* bo2    = (const float*)d_in[17];
    const float* wff1   = (const float*)d_in[18];
    const float* bff1   = (const float*)d_in[19];
    const float* wff2   = (const float*)d_in[20];
    const float* bff2   = (const float*)d_in[21];
    float* out = (float*)d_out;

    float *xp, *hp, *qp, *kp, *vp, *ap, *pp, *fp;
    cudaGetSymbolAddress((void**)&xp, g_x);
    cudaGetSymbolAddress((void**)&hp, g_h);
    cudaGetSymbolAddress((void**)&qp, g_q);
    cudaGetSymbolAddress((void**)&kp, g_k);
    cudaGetSymbolAddress((void**)&vp, g_v);
    cudaGetSymbolAddress((void**)&ap, g_attn);
    cudaGetSymbolAddress((void**)&pp, g_proj);
    cudaGetSymbolAddress((void**)&fp, g_ffh);

    cudaFuncSetAttribute(flash_tc_k,
                         cudaFuncAttributeMaxDynamicSharedMemorySize, FTC_SMEM);

    const int M  = BB * NN_;
    const long TOK = (long)M * DD;

    cudaMemcpyAsync(xp, x, TOK * sizeof(float), cudaMemcpyDeviceToDevice);

    // ===== Self-attention block =====
    ln_k<<<M, 256>>>(xp, ln1w, ln1b, hp);
    gemm_nn(hp, wq1, qp, M, DD, DD, DD, DD, DD, nullptr, nullptr);
    gemm_nn(hp, wk1, kp, M, DD, DD, DD, DD, DD, nullptr, nullptr);
    gemm_nn(hp, wv1, vp, M, DD, DD, DD, DD, DD, nullptr, nullptr);
    {
        dim3 grid(NN_ / TBM, BB * HH);
        flash_tc_k<<<grid, 256, FTC_SMEM>>>(qp, kp, vp, ap);
    }
    gemm_nn(ap, wo1, xp, M, DD, DD, DD, DD, DD, bo1, xp);

    // ===== Cross-attention block =====
    ln_k<<<M, 256>>>(xp, ln2w, ln2b, hp);
    gemm_nn(hp, wq2, qp, M, DD, DD, DD, DD, DD, nullptr, nullptr);
    gemm_nn(ctx, wk2, kp, BB * CN_, DD, CDIM, CDIM, DD, DD, nullptr, nullptr);
    gemm_nn(ctx, wv2, vp, BB * CN_, DD, CDIM, CDIM, DD, DD, nullptr, nullptr);
    xattn_k<<<BB * HH * NN_ / 8, 256>>>(qp, kp, vp, ap);
    gemm_nn(ap, wo2, xp, M, DD, DD, DD, DD, DD, bo2, xp);

    // ===== GEGLU feed-forward =====
    ln_k<<<M, 256>>>(xp, ln3w, ln3b, hp);
    gemm_nn(hp, wff1, pp, M, 2 * FF_, DD, DD, 2 * FF_, 2 * FF_, bff1, nullptr);
    {
        const long total = (long)M * FF_;
        geglu_k<<<(int)((total + 255) / 256), 256>>>(pp, fp);
    }
    gemm_nn(fp, wff2, out, M, DD, FF_, FF_, DD, DD, bff2, xp);
}

// round 6
// speedup vs baseline: 4.3318x; 1.6651x over previous
#include <cuda_runtime.h>
#include <cuda_bf16.h>
#include <math.h>
#include <stdint.h>

// ---------------------------------------------------------------------------
// Problem constants
// ---------------------------------------------------------------------------
#define BB   2
#define NN_  4096
#define DD   640
#define HH   8
#define DH   80
#define CN_  77
#define CDIM 768
#define FF_  2560
#define EPS_ 1e-5f
#define SCALE_ATTN 0.11180339887498948f   // 80^-0.5

// ---------------------------------------------------------------------------
// Device scratch (static allocation — no cudaMalloc allowed). ~370 MB total.
// ---------------------------------------------------------------------------
__device__ float g_x   [(size_t)BB * NN_ * DD];
__device__ float g_h   [(size_t)BB * NN_ * DD];
__device__ float g_q   [(size_t)BB * NN_ * DD];
__device__ float g_k   [(size_t)BB * NN_ * DD];
__device__ float g_v   [(size_t)BB * NN_ * DD];
__device__ float g_attn[(size_t)BB * NN_ * DD];
__device__ float g_proj[(size_t)BB * NN_ * 2 * FF_];
__device__ float g_ffh [(size_t)BB * NN_ * FF_];

// ---------------------------------------------------------------------------
// TF32 / cp.async helpers
// ---------------------------------------------------------------------------
__device__ __forceinline__ uint32_t f2tf32(float v) {
    uint32_t u;
    asm("cvt.rna.tf32.f32 %0, %1;" : "=r"(u) : "f"(v));
    return u;
}

__device__ __forceinline__ void mma_tf32(float* c, const uint32_t* a, const uint32_t* b) {
    asm volatile(
        "mma.sync.aligned.m16n8k8.row.col.f32.tf32.tf32.f32 "
        "{%0,%1,%2,%3}, {%4,%5,%6,%7}, {%8,%9}, {%0,%1,%2,%3};\n"
        : "+f"(c[0]), "+f"(c[1]), "+f"(c[2]), "+f"(c[3])
        : "r"(a[0]), "r"(a[1]), "r"(a[2]), "r"(a[3]),
          "r"(b[0]), "r"(b[1]));
}

__device__ __forceinline__ void cp16(uint32_t smem_addr, const void* gptr) {
    asm volatile("cp.async.ca.shared.global [%0], [%1], 16;\n"
                 :: "r"(smem_addr), "l"(gptr));
}

__device__ __forceinline__ void cp16z(uint32_t smem_addr, const void* gptr, bool valid) {
    int sz = valid ? 16 : 0;
    asm volatile("cp.async.ca.shared.global [%0], [%1], 16, %2;\n"
                 :: "r"(smem_addr), "l"(gptr), "r"(sz));
}

// ---------------------------------------------------------------------------
// TF32 tensor-core GEMM with cp.async double buffering.
//   C = A @ B (+bias) (+resid).  A row-major [M,K] lda, B row-major [K,N] ldb.
//   Requirements: K%16==0, N%128==0, lda/ldb multiples of 4.
//   Smem: As[2][128x20] (m-major, stride 20), Bs[2][16x132] (k-major, 132).
// ---------------------------------------------------------------------------
#define AST 20
#define BST 132

__global__ __launch_bounds__(256, 2)
void gemm_tf32_k(const float* __restrict__ A, const float* __restrict__ B,
                 float* __restrict__ C,
                 int M, int N, int K, int lda, int ldb, int ldc,
                 const float* __restrict__ bias,
                 const float* __restrict__ resid)
{
    __shared__ uint32_t As[2][128 * AST];
    __shared__ uint32_t Bs[2][16 * BST];

    const int tid  = threadIdx.x;
    const int wid  = tid >> 5;
    const int lane = tid & 31;
    const int g    = lane >> 2;
    const int tg   = lane & 3;
    const int wm   = wid & 3;
    const int wn   = wid >> 2;
    const int m0   = blockIdx.y * 128;
    const int n0   = blockIdx.x * 128;

    // cp.async thread mappings
    const int am = tid >> 2;             // A row for chunk 1 (chunk 2: +64)
    const int ac = (tid & 3) * 4;        // A col (float offset)
    const int bk = tid >> 5;             // B row for chunk 1 (chunk 2: +8)
    const int bc = (tid & 31) * 4;       // B col (float offset)
    const bool av0 = (m0 + am      < M);
    const bool av1 = (m0 + am + 64 < M);
    const long aoff0 = (long)(av0 ? m0 + am      : 0) * lda;
    const long aoff1 = (long)(av1 ? m0 + am + 64 : 0) * lda;

    const uint32_t asb = (uint32_t)__cvta_generic_to_shared(&As[0][0]);
    const uint32_t bsb = (uint32_t)__cvta_generic_to_shared(&Bs[0][0]);

    #define G_ISSUE(k0, buf)                                                              \
    {                                                                                      \
        cp16z(asb + (uint32_t)((buf) * 128 * AST + am * AST + ac) * 4u,                    \
              A + aoff0 + (k0) + ac, av0);                                                 \
        cp16z(asb + (uint32_t)((buf) * 128 * AST + (am + 64) * AST + ac) * 4u,             \
              A + aoff1 + (k0) + ac, av1);                                                 \
        cp16(bsb + (uint32_t)((buf) * 16 * BST + bk * BST + bc) * 4u,                      \
             B + (long)((k0) + bk) * ldb + n0 + bc);                                       \
        cp16(bsb + (uint32_t)((buf) * 16 * BST + (bk + 8) * BST + bc) * 4u,                \
             B + (long)((k0) + bk + 8) * ldb + n0 + bc);                                   \
        asm volatile("cp.async.commit_group;\n" ::);                                       \
    }

    float acc[2][8][4];
    #pragma unroll
    for (int i = 0; i < 2; i++)
        #pragma unroll
        for (int j = 0; j < 8; j++)
            #pragma unroll
            for (int q = 0; q < 4; q++) acc[i][j][q] = 0.f;

    const int NT = K / 16;
    G_ISSUE(0, 0);

    for (int kt = 0; kt < NT; kt++) {
        const int buf = kt & 1;
        __syncthreads();
        if (kt + 1 < NT) {
            G_ISSUE((kt + 1) * 16, buf ^ 1);
            asm volatile("cp.async.wait_group 1;\n" ::);
        } else {
            asm volatile("cp.async.wait_group 0;\n" ::);
        }
        __syncthreads();

        const uint32_t* Ab = As[buf];
        const uint32_t* Bb = Bs[buf];

        #pragma unroll
        for (int kk = 0; kk < 16; kk += 8) {
            uint32_t af[2][4], bf[8][2];
            #pragma unroll
            for (int mf = 0; mf < 2; mf++) {
                const int rm = wm * 32 + mf * 16 + g;
                af[mf][0] = Ab[rm       * AST + kk + tg];
                af[mf][1] = Ab[(rm + 8) * AST + kk + tg];
                af[mf][2] = Ab[rm       * AST + kk + tg + 4];
                af[mf][3] = Ab[(rm + 8) * AST + kk + tg + 4];
            }
            #pragma unroll
            for (int nf = 0; nf < 8; nf++) {
                const int cb = wn * 64 + nf * 8 + g;
                bf[nf][0] = Bb[(kk + tg)     * BST + cb];
                bf[nf][1] = Bb[(kk + tg + 4) * BST + cb];
            }
            #pragma unroll
            for (int mf = 0; mf < 2; mf++)
                #pragma unroll
                for (int nf = 0; nf < 8; nf++)
                    mma_tf32(acc[mf][nf], af[mf], bf[nf]);
        }
    }

    #pragma unroll
    for (int mf = 0; mf < 2; mf++) {
        const int r0 = m0 + wm * 32 + mf * 16 + g;
        const int r1 = r0 + 8;
        #pragma unroll
        for (int nf = 0; nf < 8; nf++) {
            const int cc = n0 + wn * 64 + nf * 8 + tg * 2;
            float b0 = 0.f, b1 = 0.f;
            if (bias) { b0 = bias[cc]; b1 = bias[cc + 1]; }
            if (r0 < M) {
                float v0 = acc[mf][nf][0] + b0;
                float v1 = acc[mf][nf][1] + b1;
                if (resid) {
                    v0 += resid[(long)r0 * ldc + cc];
                    v1 += resid[(long)r0 * ldc + cc + 1];
                }
                *(float2*)(C + (long)r0 * ldc + cc) = make_float2(v0, v1);
            }
            if (r1 < M) {
                float v0 = acc[mf][nf][2] + b0;
                float v1 = acc[mf][nf][3] + b1;
                if (resid) {
                    v0 += resid[(long)r1 * ldc + cc];
                    v1 += resid[(long)r1 * ldc + cc + 1];
                }
                *(float2*)(C + (long)r1 * ldc + cc) = make_float2(v0, v1);
            }
        }
    }
}

// ---------------------------------------------------------------------------
// TF32 tensor-core flash attention.
// ---------------------------------------------------------------------------
#define TBM 128
#define TBN 64
#define KST 84
#define VST 88
#define PST 68
#define FTC_SMEM 122880

__global__ void __launch_bounds__(256)
flash_tc_k(const float* __restrict__ Q, const float* __restrict__ K,
           const float* __restrict__ V, float* __restrict__ O)
{
    extern __shared__ uint32_t fsm[];
    uint32_t* Ps = fsm + 22016;

    const int tid  = threadIdx.x;
    const int wid  = tid >> 5;
    const int lane = tid & 31;
    const int g    = lane >> 2;
    const int tg   = lane & 3;
    const int bh   = blockIdx.y;
    const int b    = bh / HH, h = bh % HH;
    const int row0 = blockIdx.x * TBM;
    const int NT   = NN_ / TBN;

    const float* Qp = Q + (long)(b * NN_ + row0) * DD + h * DH;
    const float* Kp = K + (long)b * NN_ * DD + h * DH;
    const float* Vp = V + (long)b * NN_ * DD + h * DH;
    float*       Op = O + (long)(b * NN_ + row0) * DD + h * DH;

    const uint32_t sb = (uint32_t)__cvta_generic_to_shared(fsm);

    uint32_t qa[10][4];
    {
        const float* qw = Qp + (long)(wid * 16) * DD;
        #pragma unroll
        for (int kc = 0; kc < 10; kc++) {
            const int c0 = kc * 8 + tg;
            qa[kc][0] = f2tf32(qw[(long)g       * DD + c0]);
            qa[kc][1] = f2tf32(qw[(long)(g + 8) * DD + c0]);
            qa[kc][2] = f2tf32(qw[(long)g       * DD + c0 + 4]);
            qa[kc][3] = f2tf32(qw[(long)(g + 8) * DD + c0 + 4]);
        }
    }

    float oa[10][4];
    #pragma unroll
    for (int nf = 0; nf < 10; nf++)
        #pragma unroll
        for (int q = 0; q < 4; q++) oa[nf][q] = 0.f;
    float mr0 = -1e30f, mr1 = -1e30f, lr0 = 0.f, lr1 = 0.f;

    #define ISSUE_TILE(kt, buf)                                                          \
    {                                                                                     \
        _Pragma("unroll")                                                                 \
        for (int i = 0; i < 5; i++) {                                                     \
            const int idx = i * 256 + tid;                                                \
            const int r = idx / 20, c = idx % 20;                                         \
            cp16(sb + (uint32_t)((buf) * 5376 + r * KST + c * 4) * 4u,                    \
                 Kp + (long)((kt) * TBN + r) * DD + c * 4);                               \
        }                                                                                 \
        _Pragma("unroll")                                                                 \
        for (int i = 0; i < 5; i++) {                                                     \
            const int idx = i * 256 + tid;                                                \
            const int r = idx / 20, c = idx % 20;                                         \
            cp16(sb + (uint32_t)(10752 + (buf) * 5632 + r * VST + c * 4) * 4u,            \
                 Vp + (long)((kt) * TBN + r) * DD + c * 4);                               \
        }                                                                                 \
        asm volatile("cp.async.commit_group;\n" ::);                                      \
    }

    ISSUE_TILE(0, 0);

    for (int kt = 0; kt < NT; kt++) {
        const int buf = kt & 1;
        __syncthreads();
        if (kt + 1 < NT) {
            ISSUE_TILE(kt + 1, buf ^ 1);
            asm volatile("cp.async.wait_group 1;\n" ::);
        } else {
            asm volatile("cp.async.wait_group 0;\n" ::);
        }
        __syncthreads();

        const uint32_t* Ks = fsm + buf * 5376;
        const uint32_t* Vs = fsm + 10752 + buf * 5632;

        float sa[8][4];
        #pragma unroll
        for (int nf = 0; nf < 8; nf++)
            #pragma unroll
            for (int q = 0; q < 4; q++) sa[nf][q] = 0.f;

        #pragma unroll
        for (int kc = 0; kc < 10; kc++) {
            uint32_t bf[8][2];
            #pragma unroll
            for (int nf = 0; nf < 8; nf++) {
                bf[nf][0] = Ks[(nf * 8 + g) * KST + kc * 8 + tg];
                bf[nf][1] = Ks[(nf * 8 + g) * KST + kc * 8 + tg + 4];
            }
            #pragma unroll
            for (int nf = 0; nf < 8; nf++)
                mma_tf32(sa[nf], qa[kc], bf[nf]);
        }

        float rm0 = -1e30f, rm1 = -1e30f;
        #pragma unroll
        for (int nf = 0; nf < 8; nf++) {
            rm0 = fmaxf(rm0, fmaxf(sa[nf][0], sa[nf][1]));
            rm1 = fmaxf(rm1, fmaxf(sa[nf][2], sa[nf][3]));
        }
        rm0 *= SCALE_ATTN; rm1 *= SCALE_ATTN;
        rm0 = fmaxf(rm0, __shfl_xor_sync(0xffffffffu, rm0, 1));
        rm0 = fmaxf(rm0, __shfl_xor_sync(0xffffffffu, rm0, 2));
        rm1 = fmaxf(rm1, __shfl_xor_sync(0xffffffffu, rm1, 1));
        rm1 = fmaxf(rm1, __shfl_xor_sync(0xffffffffu, rm1, 2));

        const float mn0 = fmaxf(mr0, rm0);
        const float mn1 = fmaxf(mr1, rm1);
        const float cr0 = __expf(mr0 - mn0);
        const float cr1 = __expf(mr1 - mn1);

        float rs0 = 0.f, rs1 = 0.f;
        uint32_t* Pw0 = Ps + (wid * 16 + g) * PST;
        uint32_t* Pw1 = Ps + (wid * 16 + g + 8) * PST;
        #pragma unroll
        for (int nf = 0; nf < 8; nf++) {
            float p00 = __expf(sa[nf][0] * SCALE_ATTN - mn0);
            float p01 = __expf(sa[nf][1] * SCALE_ATTN - mn0);
            float p10 = __expf(sa[nf][2] * SCALE_ATTN - mn1);
            float p11 = __expf(sa[nf][3] * SCALE_ATTN - mn1);
            rs0 += p00 + p01;
            rs1 += p10 + p11;
            const int cc = nf * 8 + tg * 2;
            Pw0[cc]     = f2tf32(p00);
            Pw0[cc + 1] = f2tf32(p01);
            Pw1[cc]     = f2tf32(p10);
            Pw1[cc + 1] = f2tf32(p11);
        }
        rs0 += __shfl_xor_sync(0xffffffffu, rs0, 1);
        rs0 += __shfl_xor_sync(0xffffffffu, rs0, 2);
        rs1 += __shfl_xor_sync(0xffffffffu, rs1, 1);
        rs1 += __shfl_xor_sync(0xffffffffu, rs1, 2);

        lr0 = lr0 * cr0 + rs0;  mr0 = mn0;
        lr1 = lr1 * cr1 + rs1;  mr1 = mn1;

        #pragma unroll
        for (int nf = 0; nf < 10; nf++) {
            oa[nf][0] *= cr0; oa[nf][1] *= cr0;
            oa[nf][2] *= cr1; oa[nf][3] *= cr1;
        }
        __syncwarp();

        #pragma unroll
        for (int kc = 0; kc < 8; kc++) {
            uint32_t pa[4];
            pa[0] = Ps[(wid * 16 + g)     * PST + kc * 8 + tg];
            pa[1] = Ps[(wid * 16 + g + 8) * PST + kc * 8 + tg];
            pa[2] = Ps[(wid * 16 + g)     * PST + kc * 8 + tg + 4];
            pa[3] = Ps[(wid * 16 + g + 8) * PST + kc * 8 + tg + 4];
            #pragma unroll
            for (int nf = 0; nf < 10; nf++) {
                uint32_t bf[2];
                bf[0] = Vs[(kc * 8 + tg)     * VST + nf * 8 + g];
                bf[1] = Vs[(kc * 8 + tg + 4) * VST + nf * 8 + g];
                mma_tf32(oa[nf], pa, bf);
            }
        }
    }

    const float inv0 = 1.f / lr0;
    const float inv1 = 1.f / lr1;
    #pragma unroll
    for (int nf = 0; nf < 10; nf++) {
        const int cc = nf * 8 + tg * 2;
        *(float2*)(Op + (long)(wid * 16 + g)     * DD + cc) =
            make_float2(oa[nf][0] * inv0, oa[nf][1] * inv0);
        *(float2*)(Op + (long)(wid * 16 + g + 8) * DD + cc) =
            make_float2(oa[nf][2] * inv1, oa[nf][3] * inv1);
    }
}

// ---------------------------------------------------------------------------
// LayerNorm: one warp per row (640 = 32 lanes x 5 float4).
// ---------------------------------------------------------------------------
__global__ __launch_bounds__(256)
void ln_k(const float* __restrict__ x, const float* __restrict__ w,
          const float* __restrict__ b, float* __restrict__ out)
{
    const int lane = threadIdx.x & 31;
    const long row = (long)blockIdx.x * 8 + (threadIdx.x >> 5);
    const float4* p = (const float4*)(x + row * DD);

    float4 v[5];
    float s = 0.f, ss = 0.f;
    #pragma unroll
    for (int i = 0; i < 5; i++) {
        v[i] = p[i * 32 + lane];
        s  += v[i].x + v[i].y + v[i].z + v[i].w;
        ss += v[i].x * v[i].x + v[i].y * v[i].y + v[i].z * v[i].z + v[i].w * v[i].w;
    }
    #pragma unroll
    for (int o = 16; o > 0; o >>= 1) {
        s  += __shfl_xor_sync(0xffffffffu, s,  o);
        ss += __shfl_xor_sync(0xffffffffu, ss, o);
    }
    const float mean = s * (1.f / DD);
    const float var  = ss * (1.f / DD) - mean * mean;
    const float inv  = rsqrtf(var + EPS_);

    float4* o4 = (float4*)(out + row * DD);
    const float4* w4 = (const float4*)w;
    const float4* b4 = (const float4*)b;
    #pragma unroll
    for (int i = 0; i < 5; i++) {
        const int c = i * 32 + lane;
        float4 wv = w4[c], bv = b4[c], r;
        r.x = (v[i].x - mean) * inv * wv.x + bv.x;
        r.y = (v[i].y - mean) * inv * wv.y + bv.y;
        r.z = (v[i].z - mean) * inv * wv.z + bv.z;
        r.w = (v[i].w - mean) * inv * wv.w + bv.w;
        o4[c] = r;
    }
}

// ---------------------------------------------------------------------------
// Cross-attention with smem-resident K/V.
// ---------------------------------------------------------------------------
#define XSMEM_BYTES 54720

__global__ __launch_bounds__(256)
void xattn_k(const float* __restrict__ Q, const float* __restrict__ K,
             const float* __restrict__ V, float* __restrict__ O)
{
    extern __shared__ float xs[];
    float* Ks = xs;            // stride 81
    float* Vs = xs + 6240;     // stride 80
    float* sc = xs + 12400;    // [8][80]
    float* qb = xs + 13040;    // [8][80]

    const int tid  = threadIdx.x;
    const int wid  = tid >> 5;
    const int lane = tid & 31;
    const int bh   = blockIdx.y;
    const int b    = bh / HH, h = bh % HH;
    const int q0   = blockIdx.x * 128;

    const float* Kp = K + (long)b * CN_ * DD + h * DH;
    const float* Vp = V + (long)b * CN_ * DD + h * DH;
    for (int idx = tid; idx < CN_ * DH; idx += 256) {
        const int j = idx / DH, d = idx % DH;
        Ks[j * 81 + d] = Kp[(long)j * DD + d];
        Vs[j * 80 + d] = Vp[(long)j * DD + d];
    }
    __syncthreads();

    float* scw = sc + wid * 80;
    float* qbw = qb + wid * 80;

    for (int qq = wid; qq < 128; qq += 8) {
        const int qrow = q0 + qq;
        const float* qp = Q + ((long)(b * NN_ + qrow) * DD + h * DH);
        for (int d = lane; d < DH; d += 32) qbw[d] = qp[d];
        __syncwarp();

        float mx = -1e30f;
        for (int j = lane; j < CN_; j += 32) {
            float s = 0.f;
            #pragma unroll 8
            for (int d = 0; d < DH; d++) s += qbw[d] * Ks[j * 81 + d];
            s *= SCALE_ATTN;
            scw[j] = s;
            mx = fmaxf(mx, s);
        }
        #pragma unroll
        for (int o = 16; o > 0; o >>= 1)
            mx = fmaxf(mx, __shfl_xor_sync(0xffffffffu, mx, o));

        float sum = 0.f;
        __syncwarp();
        for (int j = lane; j < CN_; j += 32) {
            float e = __expf(scw[j] - mx);
            scw[j] = e;
            sum += e;
        }
        #pragma unroll
        for (int o = 16; o > 0; o >>= 1)
            sum += __shfl_xor_sync(0xffffffffu, sum, o);
        const float inv = 1.f / sum;
        __syncwarp();

        float* op = O + ((long)(b * NN_ + qrow) * DD + h * DH);
        for (int d = lane; d < DH; d += 32) {
            float acc = 0.f;
            #pragma unroll 7
            for (int j = 0; j < CN_; j++) acc += scw[j] * Vs[j * 80 + d];
            op[d] = acc * inv;
        }
        __syncwarp();
    }
}

// ---------------------------------------------------------------------------
// GEGLU (float4)
// ---------------------------------------------------------------------------
__device__ __forceinline__ float gelu1(float g) {
    return 0.5f * g * (1.f + erff(g * 0.70710678118654752f));
}

__global__ __launch_bounds__(256)
void geglu_k(const float4* __restrict__ proj, float4* __restrict__ out)
{
    const long idx = (long)blockIdx.x * 256 + threadIdx.x;
    const long row = idx / (FF_ / 4);
    const long c   = idx % (FF_ / 4);
    const float4 a = proj[row * (2 * FF_ / 4) + c];
    const float4 g = proj[row * (2 * FF_ / 4) + FF_ / 4 + c];
    float4 r;
    r.x = a.x * gelu1(g.x);
    r.y = a.y * gelu1(g.y);
    r.z = a.z * gelu1(g.z);
    r.w = a.w * gelu1(g.w);
    out[idx] = r;
}

// ---------------------------------------------------------------------------
// Host-side launch helpers
// ---------------------------------------------------------------------------
static inline void gemm_nn(const float* A, const float* B, float* C,
                           int M, int N, int K, int lda, int ldb, int ldc,
                           const float* bias, const float* resid)
{
    dim3 grid(N / 128, (M + 127) / 128, 1);
    gemm_tf32_k<<<grid, 256>>>(A, B, C, M, N, K, lda, ldb, ldc, bias, resid);
}

extern "C" void kernel_launch(void* const* d_in, const int* in_sizes, int n_in,
                              void* d_out, int out_size)
{
    const float* x      = (const float*)d_in[0];
    const float* ctx    = (const float*)d_in[1];
    const float* ln1w   = (const float*)d_in[2];
    const float* ln1b   = (const float*)d_in[3];
    const float* ln2w   = (const float*)d_in[4];
    const float* ln2b   = (const float*)d_in[5];
    const float* ln3w   = (const float*)d_in[6];
    const float* ln3b   = (const float*)d_in[7];
    const float* wq1    = (const float*)d_in[8];
    const float* wk1    = (const float*)d_in[9];
    const float* wv1    = (const float*)d_in[10];
    const float* wo1    = (const float*)d_in[11];
    const float* bo1    = (const float*)d_in[12];
    const float* wq2    = (const float*)d_in[13];
    const float* wk2    = (const float*)d_in[14];
    const float* wv2    = (const float*)d_in[15];
    const float* wo2    = (const float*)d_in[16];
    const float* bo2    = (const float*)d_in[17];
    const float* wff1   = (const float*)d_in[18];
    const float* bff1   = (const float*)d_in[19];
    const float* wff2   = (const float*)d_in[20];
    const float* bff2   = (const float*)d_in[21];
    float* out = (float*)d_out;

    float *xp, *hp, *qp, *kp, *vp, *ap, *pp, *fp;
    cudaGetSymbolAddress((void**)&xp, g_x);
    cudaGetSymbolAddress((void**)&hp, g_h);
    cudaGetSymbolAddress((void**)&qp, g_q);
    cudaGetSymbolAddress((void**)&kp, g_k);
    cudaGetSymbolAddress((void**)&vp, g_v);
    cudaGetSymbolAddress((void**)&ap, g_attn);
    cudaGetSymbolAddress((void**)&pp, g_proj);
    cudaGetSymbolAddress((void**)&fp, g_ffh);

    cudaFuncSetAttribute(flash_tc_k,
                         cudaFuncAttributeMaxDynamicSharedMemorySize, FTC_SMEM);
    cudaFuncSetAttribute(xattn_k,
                         cudaFuncAttributeMaxDynamicSharedMemorySize, XSMEM_BYTES);

    const int M  = BB * NN_;
    const long TOK = (long)M * DD;

    cudaMemcpyAsync(xp, x, TOK * sizeof(float), cudaMemcpyDeviceToDevice);

    // ===== Self-attention block =====
    ln_k<<<M / 8, 256>>>(xp, ln1w, ln1b, hp);
    gemm_nn(hp, wq1, qp, M, DD, DD, DD, DD, DD, nullptr, nullptr);
    gemm_nn(hp, wk1, kp, M, DD, DD, DD, DD, DD, nullptr, nullptr);
    gemm_nn(hp, wv1, vp, M, DD, DD, DD, DD, DD, nullptr, nullptr);
    {
        dim3 grid(NN_ / TBM, BB * HH);
        flash_tc_k<<<grid, 256, FTC_SMEM>>>(qp, kp, vp, ap);
    }
    gemm_nn(ap, wo1, xp, M, DD, DD, DD, DD, DD, bo1, xp);

    // ===== Cross-attention block =====
    ln_k<<<M / 8, 256>>>(xp, ln2w, ln2b, hp);
    gemm_nn(hp, wq2, qp, M, DD, DD, DD, DD, DD, nullptr, nullptr);
    gemm_nn(ctx, wk2, kp, BB * CN_, DD, CDIM, CDIM, DD, DD, nullptr, nullptr);
    gemm_nn(ctx, wv2, vp, BB * CN_, DD, CDIM, CDIM, DD, DD, nullptr, nullptr);
    {
        dim3 grid(NN_ / 128, BB * HH);
        xattn_k<<<grid, 256, XSMEM_BYTES>>>(qp, kp, vp, ap);
    }
    gemm_nn(ap, wo2, xp, M, DD, DD, DD, DD, DD, bo2, xp);

    // ===== GEGLU feed-forward =====
    ln_k<<<M / 8, 256>>>(xp, ln3w, ln3b, hp);
    gemm_nn(hp, wff1, pp, M, 2 * FF_, DD, DD, 2 * FF_, 2 * FF_, bff1, nullptr);
    {
        const long total4 = (long)M * (FF_ / 4);
        geglu_k<<<(int)(total4 / 256), 256>>>((const float4*)pp, (float4*)fp);
    }
    gemm_nn(fp, wff2, out, M, DD, FF_, FF_, DD, DD, bff2, xp);
}